// round 5
// baseline (speedup 1.0000x reference)
#include <cuda_runtime.h>

// out[b,o] = ( x @ softmax(W,axis=1)^T > 0.5 )
// BIT-REPLICATION constraints (verified: 1 flip @ rel_err 4.888e-4):
//  - softmax: XLA row-reduction tree replica (kernel 1, DO NOT REORDER)
//  - GEMM: per-output serial ascending-k fp32 fma.rn chain.
// This round: packed fma.rn.f32x2 (2 independent IEEE fp32 FMA lanes per
// instruction) pairing adjacent-N accumulators -> same per-output chain,
// ~36% fewer issue slots.
//
// d_in[0] = x [4096,2048] f32 (0/1), d_in[1] = raw_weight [2048,2048] f32

#define M_DIM 4096
#define N_DIM 2048
#define K_DIM 2048

__device__ float g_w[(size_t)N_DIM * K_DIM];

// ---------------------------------------------------------------------------
// Kernel 1: XLA softmax replica (unchanged — bit-exact anchor).
// ---------------------------------------------------------------------------
__global__ __launch_bounds__(1024) void softmax_rows_kernel(const float* __restrict__ raw) {
    const int row = blockIdx.x;
    const int tid = threadIdx.x;
    const int lane = tid & 31;
    const int wid = tid >> 5;

    const float2* __restrict__ r2 =
        reinterpret_cast<const float2*>(raw + (size_t)row * K_DIM);
    float2* __restrict__ w2 = reinterpret_cast<float2*>(g_w + (size_t)row * K_DIM);

    const float2 v = r2[tid];

    __shared__ float s_part[32];
    __shared__ float s_bcast;

    float m = fmaxf(v.x, v.y);
#pragma unroll
    for (int off = 16; off > 0; off >>= 1)
        m = fmaxf(m, __shfl_down_sync(0xffffffffu, m, off));
    if (lane == 0) s_part[wid] = m;
    __syncthreads();
    if (wid == 0) {
        float t = s_part[lane];
#pragma unroll
        for (int off = 16; off > 0; off >>= 1)
            t = fmaxf(t, __shfl_down_sync(0xffffffffu, t, off));
        if (lane == 0) s_bcast = t;
    }
    __syncthreads();
    m = s_bcast;
    __syncthreads();

    const float e0 = expf(v.x - m);
    const float e1 = expf(v.y - m);

    float p = e0 + e1;
#pragma unroll
    for (int off = 16; off > 0; off >>= 1)
        p += __shfl_down_sync(0xffffffffu, p, off);
    if (lane == 0) s_part[wid] = p;
    __syncthreads();
    if (wid == 0) {
        float t = s_part[lane];
#pragma unroll
        for (int off = 16; off > 0; off >>= 1)
            t += __shfl_down_sync(0xffffffffu, t, off);
        if (lane == 0) s_bcast = t;
    }
    __syncthreads();
    const float S = s_bcast;

    float2 w;
    w.x = e0 / S;
    w.y = e1 / S;
    w2[tid] = w;
}

// ---------------------------------------------------------------------------
// Kernel 2: FFMA2 GEMM + threshold.
// 128x128 tile, BK=16, 256 threads, 8x8 microtile as 8x4 packed-pair accs.
// A stored DUPLICATED in smem (As2[k][2m]=As2[k][2m+1]=a) so the {a,a}
// broadcast pair is a single LDS.64. B pairs come free via ulonglong2 LDS.128.
// Smem: As2 2*16*256*4 = 32KB, Bs 2*16*128*4 = 16KB -> exactly 48KB static.
// ---------------------------------------------------------------------------
#define BM 128
#define BN 128
#define BK 16
#define LDA2 256  // duplicated-A row: 2*128 floats (1024B, 16B-aligned)
#define LDB 128
#define NKT (K_DIM / BK)

typedef unsigned long long u64t;

__device__ __forceinline__ u64t dup_f32(float f) {
    u64t r;
    asm("mov.b64 %0, {%1, %1};" : "=l"(r) : "f"(f));
    return r;
}

#define FMA2(acc, a, b) \
    asm("fma.rn.f32x2 %0, %1, %2, %0;" : "+l"(acc) : "l"(a), "l"(b))

#define FMA2_ROW(i)            \
    FMA2(acc2[i][0], ap[i], bq0.x); \
    FMA2(acc2[i][1], ap[i], bq0.y); \
    FMA2(acc2[i][2], ap[i], bq1.x); \
    FMA2(acc2[i][3], ap[i], bq1.y);

__global__ __launch_bounds__(256, 2) void gemm_thresh_kernel(const float* __restrict__ A,
                                                             float* __restrict__ C) {
    const float* __restrict__ B = g_w;

    __shared__ float As2[2][BK][LDA2];
    __shared__ float Bs[2][BK][LDB];

    const int tid = threadIdx.x;
    const int bm = blockIdx.y * BM;
    const int bn = blockIdx.x * BN;

    const int lrow0 = tid >> 2;        // 0..63
    const int lrow1 = lrow0 + 64;      // 64..127
    const int lcol = (tid & 3) * 4;    // 0,4,8,12

    const int ty = tid >> 4;  // 0..15 (M)
    const int tx = tid & 15;  // 0..15 (N)

    u64t acc2[8][4];
#pragma unroll
    for (int i = 0; i < 8; ++i)
#pragma unroll
        for (int j = 0; j < 4; ++j) acc2[i][j] = 0ull;  // (0.0f, 0.0f)

    const float* __restrict__ Ap0 = A + (size_t)(bm + lrow0) * K_DIM + lcol;
    const float* __restrict__ Ap1 = A + (size_t)(bm + lrow1) * K_DIM + lcol;
    const float* __restrict__ Bp0 = B + (size_t)(bn + lrow0) * K_DIM + lcol;
    const float* __restrict__ Bp1 = B + (size_t)(bn + lrow1) * K_DIM + lcol;

    float4 pa0 = *(const float4*)(Ap0);
    float4 pa1 = *(const float4*)(Ap1);
    float4 pb0 = *(const float4*)(Bp0);
    float4 pb1 = *(const float4*)(Bp1);

    int buf = 0;
    // A duplicated stores (STS.64 of {a,a}); B scalar stores (transposed).
    *(u64t*)&As2[0][lcol + 0][2 * lrow0] = dup_f32(pa0.x);
    *(u64t*)&As2[0][lcol + 1][2 * lrow0] = dup_f32(pa0.y);
    *(u64t*)&As2[0][lcol + 2][2 * lrow0] = dup_f32(pa0.z);
    *(u64t*)&As2[0][lcol + 3][2 * lrow0] = dup_f32(pa0.w);
    *(u64t*)&As2[0][lcol + 0][2 * lrow1] = dup_f32(pa1.x);
    *(u64t*)&As2[0][lcol + 1][2 * lrow1] = dup_f32(pa1.y);
    *(u64t*)&As2[0][lcol + 2][2 * lrow1] = dup_f32(pa1.z);
    *(u64t*)&As2[0][lcol + 3][2 * lrow1] = dup_f32(pa1.w);
    Bs[0][lcol + 0][lrow0] = pb0.x; Bs[0][lcol + 1][lrow0] = pb0.y;
    Bs[0][lcol + 2][lrow0] = pb0.z; Bs[0][lcol + 3][lrow0] = pb0.w;
    Bs[0][lcol + 0][lrow1] = pb1.x; Bs[0][lcol + 1][lrow1] = pb1.y;
    Bs[0][lcol + 2][lrow1] = pb1.z; Bs[0][lcol + 3][lrow1] = pb1.w;
    __syncthreads();

    for (int kt = 0; kt < NKT; ++kt) {
        const int ko = (kt + 1) * BK;
        const bool has_next = (kt + 1 < NKT);
        if (has_next) {
            pa0 = *(const float4*)(Ap0 + ko);
            pa1 = *(const float4*)(Ap1 + ko);
            pb0 = *(const float4*)(Bp0 + ko);
            pb1 = *(const float4*)(Bp1 + ko);
        }

#pragma unroll
        for (int k = 0; k < BK; ++k) {  // k strictly ascending: serial chain
            u64t ap[8];
#pragma unroll
            for (int i = 0; i < 4; ++i)
                ap[i] = *(const u64t*)&As2[buf][k][(ty * 4 + i) * 2];
#pragma unroll
            for (int i = 0; i < 4; ++i)
                ap[4 + i] = *(const u64t*)&As2[buf][k][(64 + ty * 4 + i) * 2];
            const ulonglong2 bq0 = *(const ulonglong2*)&Bs[buf][k][tx * 4];
            const ulonglong2 bq1 = *(const ulonglong2*)&Bs[buf][k][64 + tx * 4];
            FMA2_ROW(0)
            FMA2_ROW(1)
            FMA2_ROW(2)
            FMA2_ROW(3)
            FMA2_ROW(4)
            FMA2_ROW(5)
            FMA2_ROW(6)
            FMA2_ROW(7)
        }

        if (has_next) {
            buf ^= 1;
            *(u64t*)&As2[buf][lcol + 0][2 * lrow0] = dup_f32(pa0.x);
            *(u64t*)&As2[buf][lcol + 1][2 * lrow0] = dup_f32(pa0.y);
            *(u64t*)&As2[buf][lcol + 2][2 * lrow0] = dup_f32(pa0.z);
            *(u64t*)&As2[buf][lcol + 3][2 * lrow0] = dup_f32(pa0.w);
            *(u64t*)&As2[buf][lcol + 0][2 * lrow1] = dup_f32(pa1.x);
            *(u64t*)&As2[buf][lcol + 1][2 * lrow1] = dup_f32(pa1.y);
            *(u64t*)&As2[buf][lcol + 2][2 * lrow1] = dup_f32(pa1.z);
            *(u64t*)&As2[buf][lcol + 3][2 * lrow1] = dup_f32(pa1.w);
            Bs[buf][lcol + 0][lrow0] = pb0.x; Bs[buf][lcol + 1][lrow0] = pb0.y;
            Bs[buf][lcol + 2][lrow0] = pb0.z; Bs[buf][lcol + 3][lrow0] = pb0.w;
            Bs[buf][lcol + 0][lrow1] = pb1.x; Bs[buf][lcol + 1][lrow1] = pb1.y;
            Bs[buf][lcol + 2][lrow1] = pb1.z; Bs[buf][lcol + 3][lrow1] = pb1.w;
            __syncthreads();
        }
    }

    // Epilogue: unpack pairs, threshold at 0.5, vector stores.
#pragma unroll
    for (int i = 0; i < 8; ++i) {
        const int m = bm + ((i < 4) ? (ty * 4 + i) : (64 + ty * 4 + (i - 4)));
        float c[8];
#pragma unroll
        for (int j = 0; j < 4; ++j) {
            float lo, hi;
            asm("mov.b64 {%0, %1}, %2;" : "=f"(lo), "=f"(hi) : "l"(acc2[i][j]));
            c[2 * j] = lo;
            c[2 * j + 1] = hi;
        }
        float4 o0, o1;
        o0.x = c[0] > 0.5f ? 1.f : 0.f;
        o0.y = c[1] > 0.5f ? 1.f : 0.f;
        o0.z = c[2] > 0.5f ? 1.f : 0.f;
        o0.w = c[3] > 0.5f ? 1.f : 0.f;
        o1.x = c[4] > 0.5f ? 1.f : 0.f;
        o1.y = c[5] > 0.5f ? 1.f : 0.f;
        o1.z = c[6] > 0.5f ? 1.f : 0.f;
        o1.w = c[7] > 0.5f ? 1.f : 0.f;
        *(float4*)&C[(size_t)m * N_DIM + bn + tx * 4] = o0;
        *(float4*)&C[(size_t)m * N_DIM + bn + 64 + tx * 4] = o1;
    }
}

// ---------------------------------------------------------------------------
extern "C" void kernel_launch(void* const* d_in, const int* in_sizes, int n_in,
                              void* d_out, int out_size) {
    const float* x = (const float*)d_in[0];      // [4096, 2048]
    const float* raw_w = (const float*)d_in[1];  // [2048, 2048]
    float* out = (float*)d_out;                  // [4096, 2048]

    softmax_rows_kernel<<<N_DIM, 1024>>>(raw_w);

    dim3 grid(N_DIM / BN, M_DIM / BM);  // (16, 32)
    gemm_thresh_kernel<<<grid, 256>>>(x, out);
}

// round 6
// speedup vs baseline: 1.3315x; 1.3315x over previous
#include <cuda_runtime.h>

// out[b,o] = ( x @ softmax(W,axis=1)^T > 0.5 )
// BIT-REPLICATION constraints (verified: 1 flip @ rel_err 4.888e-4):
//  - softmax: XLA row-reduction tree replica (kernel 1, DO NOT REORDER)
//  - GEMM: per-output serial ascending-k fp32 fma.rn chain (FFMA2 lanes are
//    independent IEEE fma.rn -> chain preserved).
// R6: FFMA2 GEMM, A loaded via normal LDS.128, {a,a} pairs built by register
// MOVs (no smem duplication) -> smem wavefronts back to R4 level.

#define M_DIM 4096
#define N_DIM 2048
#define K_DIM 2048

__device__ float g_w[(size_t)N_DIM * K_DIM];

// ---------------------------------------------------------------------------
// Kernel 1: XLA softmax replica (unchanged — bit-exact anchor).
// ---------------------------------------------------------------------------
__global__ __launch_bounds__(1024) void softmax_rows_kernel(const float* __restrict__ raw) {
    const int row = blockIdx.x;
    const int tid = threadIdx.x;
    const int lane = tid & 31;
    const int wid = tid >> 5;

    const float2* __restrict__ r2 =
        reinterpret_cast<const float2*>(raw + (size_t)row * K_DIM);
    float2* __restrict__ w2 = reinterpret_cast<float2*>(g_w + (size_t)row * K_DIM);

    const float2 v = r2[tid];

    __shared__ float s_part[32];
    __shared__ float s_bcast;

    float m = fmaxf(v.x, v.y);
#pragma unroll
    for (int off = 16; off > 0; off >>= 1)
        m = fmaxf(m, __shfl_down_sync(0xffffffffu, m, off));
    if (lane == 0) s_part[wid] = m;
    __syncthreads();
    if (wid == 0) {
        float t = s_part[lane];
#pragma unroll
        for (int off = 16; off > 0; off >>= 1)
            t = fmaxf(t, __shfl_down_sync(0xffffffffu, t, off));
        if (lane == 0) s_bcast = t;
    }
    __syncthreads();
    m = s_bcast;
    __syncthreads();

    const float e0 = expf(v.x - m);
    const float e1 = expf(v.y - m);

    float p = e0 + e1;
#pragma unroll
    for (int off = 16; off > 0; off >>= 1)
        p += __shfl_down_sync(0xffffffffu, p, off);
    if (lane == 0) s_part[wid] = p;
    __syncthreads();
    if (wid == 0) {
        float t = s_part[lane];
#pragma unroll
        for (int off = 16; off > 0; off >>= 1)
            t += __shfl_down_sync(0xffffffffu, t, off);
        if (lane == 0) s_bcast = t;
    }
    __syncthreads();
    const float S = s_bcast;

    float2 w;
    w.x = e0 / S;
    w.y = e1 / S;
    w2[tid] = w;
}

// ---------------------------------------------------------------------------
// Kernel 2: FFMA2 GEMM + threshold.
// 128x128 tile, BK=16, 256 threads, 8x8 microtile as 8x4 packed N-pairs.
// A/B in smem exactly as R4 (transposed, padded). Per k-step:
//   2 LDS.128 (A) + 2 LDS.128 (B pairs free) + 16 MOV ({a,a} dup) + 32 FFMA2.
// ---------------------------------------------------------------------------
#define BM 128
#define BN 128
#define BK 16
#define LDA (BM + 4)
#define NKT (K_DIM / BK)

typedef unsigned long long u64t;

__device__ __forceinline__ u64t dup_f32(float f) {
    u64t r;
    asm("mov.b64 %0, {%1, %1};" : "=l"(r) : "f"(f));
    return r;
}

#define FMA2(acc, a, b) \
    asm("fma.rn.f32x2 %0, %1, %2, %0;" : "+l"(acc) : "l"(a), "l"(b))

#define FMA2_ROW(i, ap)            \
    FMA2(acc2[i][0], ap, bq0.x);   \
    FMA2(acc2[i][1], ap, bq0.y);   \
    FMA2(acc2[i][2], ap, bq1.x);   \
    FMA2(acc2[i][3], ap, bq1.y);

__global__ __launch_bounds__(256, 2) void gemm_thresh_kernel(const float* __restrict__ A,
                                                             float* __restrict__ C) {
    const float* __restrict__ B = g_w;

    __shared__ float As[2][BK][LDA];
    __shared__ float Bs[2][BK][LDA];

    const int tid = threadIdx.x;
    const int bm = blockIdx.y * BM;
    const int bn = blockIdx.x * BN;

    const int lrow0 = tid >> 2;
    const int lrow1 = lrow0 + 64;
    const int lcol = (tid & 3) * 4;

    const int ty = tid >> 4;  // 0..15 (M)
    const int tx = tid & 15;  // 0..15 (N)

    u64t acc2[8][4];
#pragma unroll
    for (int i = 0; i < 8; ++i)
#pragma unroll
        for (int j = 0; j < 4; ++j) acc2[i][j] = 0ull;  // (0.0f, 0.0f)

    const float* __restrict__ Ap0 = A + (size_t)(bm + lrow0) * K_DIM + lcol;
    const float* __restrict__ Ap1 = A + (size_t)(bm + lrow1) * K_DIM + lcol;
    const float* __restrict__ Bp0 = B + (size_t)(bn + lrow0) * K_DIM + lcol;
    const float* __restrict__ Bp1 = B + (size_t)(bn + lrow1) * K_DIM + lcol;

    float4 pa0 = *(const float4*)(Ap0);
    float4 pa1 = *(const float4*)(Ap1);
    float4 pb0 = *(const float4*)(Bp0);
    float4 pb1 = *(const float4*)(Bp1);

    int buf = 0;
    As[0][lcol + 0][lrow0] = pa0.x; As[0][lcol + 1][lrow0] = pa0.y;
    As[0][lcol + 2][lrow0] = pa0.z; As[0][lcol + 3][lrow0] = pa0.w;
    As[0][lcol + 0][lrow1] = pa1.x; As[0][lcol + 1][lrow1] = pa1.y;
    As[0][lcol + 2][lrow1] = pa1.z; As[0][lcol + 3][lrow1] = pa1.w;
    Bs[0][lcol + 0][lrow0] = pb0.x; Bs[0][lcol + 1][lrow0] = pb0.y;
    Bs[0][lcol + 2][lrow0] = pb0.z; Bs[0][lcol + 3][lrow0] = pb0.w;
    Bs[0][lcol + 0][lrow1] = pb1.x; Bs[0][lcol + 1][lrow1] = pb1.y;
    Bs[0][lcol + 2][lrow1] = pb1.z; Bs[0][lcol + 3][lrow1] = pb1.w;
    __syncthreads();

    for (int kt = 0; kt < NKT; ++kt) {
        const int ko = (kt + 1) * BK;
        const bool has_next = (kt + 1 < NKT);
        if (has_next) {
            pa0 = *(const float4*)(Ap0 + ko);
            pa1 = *(const float4*)(Ap1 + ko);
            pb0 = *(const float4*)(Bp0 + ko);
            pb1 = *(const float4*)(Bp1 + ko);
        }

#pragma unroll
        for (int k = 0; k < BK; ++k) {  // k strictly ascending: serial chain
            const float4 a0 = *(const float4*)&As[buf][k][ty * 4];
            const float4 a1 = *(const float4*)&As[buf][k][64 + ty * 4];
            const ulonglong2 bq0 = *(const ulonglong2*)&Bs[buf][k][tx * 4];
            const ulonglong2 bq1 = *(const ulonglong2*)&Bs[buf][k][64 + tx * 4];
            FMA2_ROW(0, dup_f32(a0.x))
            FMA2_ROW(1, dup_f32(a0.y))
            FMA2_ROW(2, dup_f32(a0.z))
            FMA2_ROW(3, dup_f32(a0.w))
            FMA2_ROW(4, dup_f32(a1.x))
            FMA2_ROW(5, dup_f32(a1.y))
            FMA2_ROW(6, dup_f32(a1.z))
            FMA2_ROW(7, dup_f32(a1.w))
        }

        if (has_next) {
            buf ^= 1;
            As[buf][lcol + 0][lrow0] = pa0.x; As[buf][lcol + 1][lrow0] = pa0.y;
            As[buf][lcol + 2][lrow0] = pa0.z; As[buf][lcol + 3][lrow0] = pa0.w;
            As[buf][lcol + 0][lrow1] = pa1.x; As[buf][lcol + 1][lrow1] = pa1.y;
            As[buf][lcol + 2][lrow1] = pa1.z; As[buf][lcol + 3][lrow1] = pa1.w;
            Bs[buf][lcol + 0][lrow0] = pb0.x; Bs[buf][lcol + 1][lrow0] = pb0.y;
            Bs[buf][lcol + 2][lrow0] = pb0.z; Bs[buf][lcol + 3][lrow0] = pb0.w;
            Bs[buf][lcol + 0][lrow1] = pb1.x; Bs[buf][lcol + 1][lrow1] = pb1.y;
            Bs[buf][lcol + 2][lrow1] = pb1.z; Bs[buf][lcol + 3][lrow1] = pb1.w;
            __syncthreads();
        }
    }

    // Epilogue: unpack pairs, threshold at 0.5, vector stores.
#pragma unroll
    for (int i = 0; i < 8; ++i) {
        const int m = bm + ((i < 4) ? (ty * 4 + i) : (64 + ty * 4 + (i - 4)));
        float c[8];
#pragma unroll
        for (int j = 0; j < 4; ++j) {
            float lo, hi;
            asm("mov.b64 {%0, %1}, %2;" : "=f"(lo), "=f"(hi) : "l"(acc2[i][j]));
            c[2 * j] = lo;
            c[2 * j + 1] = hi;
        }
        float4 o0, o1;
        o0.x = c[0] > 0.5f ? 1.f : 0.f;
        o0.y = c[1] > 0.5f ? 1.f : 0.f;
        o0.z = c[2] > 0.5f ? 1.f : 0.f;
        o0.w = c[3] > 0.5f ? 1.f : 0.f;
        o1.x = c[4] > 0.5f ? 1.f : 0.f;
        o1.y = c[5] > 0.5f ? 1.f : 0.f;
        o1.z = c[6] > 0.5f ? 1.f : 0.f;
        o1.w = c[7] > 0.5f ? 1.f : 0.f;
        *(float4*)&C[(size_t)m * N_DIM + bn + tx * 4] = o0;
        *(float4*)&C[(size_t)m * N_DIM + bn + 64 + tx * 4] = o1;
    }
}

// ---------------------------------------------------------------------------
extern "C" void kernel_launch(void* const* d_in, const int* in_sizes, int n_in,
                              void* d_out, int out_size) {
    const float* x = (const float*)d_in[0];      // [4096, 2048]
    const float* raw_w = (const float*)d_in[1];  // [2048, 2048]
    float* out = (float*)d_out;                  // [4096, 2048]

    softmax_rows_kernel<<<N_DIM, 1024>>>(raw_w);

    dim3 grid(N_DIM / BN, M_DIM / BM);  // (16, 32)
    gemm_thresh_kernel<<<grid, 256>>>(x, out);
}